// round 4
// baseline (speedup 1.0000x reference)
#include <cuda_runtime.h>
#include <cuda_bf16.h>

#define NN 262144
#define DD 1024
#define GG 1024
#define NA 17
#define EPS 1e-5f

// ---------------- scratch (device globals; no allocation allowed) -------------
__device__ int   d_starts[GG + 1];
__device__ float d_stats[GG * 56];
__device__ float d_pooled[GG * DD];                // 4 MB
__device__ float d_part[4 * 1024 * 1024];          // 16 MB split-K partials (reused)
__device__ float d_r0[GG * (DD / 2)];
__device__ float d_r1[GG * (DD / 4)];
__device__ float d_bnsum[8 * (DD / 2)];
__device__ float d_bnsq[8 * (DD / 2)];
__device__ float d_scale[DD / 2];
__device__ float d_shift[DD / 2];
__device__ float d_w1p[(DD / 2) * (DD / 4)];       // scale-folded fc1_W
__device__ float d_b1p[DD / 4];                    // shift-folded fc1 bias

#define FMA2(c, a, b) asm("fma.rn.f32x2 %0, %1, %2, %0;" : "+l"(c) : "l"(a), "l"(b))

__device__ __forceinline__ unsigned long long pack2(float lo, float hi) {
    unsigned long long r;
    asm("mov.b64 %0, {%1, %2};" : "=l"(r) : "f"(lo), "f"(hi));
    return r;
}
__device__ __forceinline__ void unpack2(unsigned long long v, float& lo, float& hi) {
    asm("mov.b64 {%0, %1}, %2;" : "=f"(lo), "=f"(hi) : "l"(v));
}

// ---------------- K1: segment starts ------------------------------------------
__global__ void k_find_starts(const int* __restrict__ batch) {
    int i = blockIdx.x * blockDim.x + threadIdx.x;
    if (i > GG) return;
    int lo = 0, hi = NN;
    while (lo < hi) {
        int mid = (lo + hi) >> 1;
        if (batch[mid] < i) lo = mid + 1; else hi = mid;
    }
    d_starts[i] = lo;
}

// ---------------- K2: per-graph attr stats ------------------------------------
__global__ void k_stats(const float* __restrict__ attr, const int* __restrict__ ntype) {
    int gph = blockIdx.x;
    int s0 = d_starts[gph], s1 = d_starts[gph + 1];

    float a0[NA], a1[NA], c2[NA];
    #pragma unroll
    for (int k = 0; k < NA; k++) { a0[k] = 0.f; a1[k] = 0.f; c2[k] = 0.f; }
    float n0 = 0.f, n1 = 0.f;

    for (int r = s0 + threadIdx.x; r < s1; r += blockDim.x) {
        int t = ntype[r];
        const float* ar = attr + (long)r * NA;
        float av[NA];
        #pragma unroll
        for (int k = 0; k < NA; k++) av[k] = ar[k];
        if (t == 0) {
            n0 += 1.f;
            #pragma unroll
            for (int k = 0; k < NA; k++) a0[k] += av[k];
        } else if (t == 1) {
            n1 += 1.f;
            #pragma unroll
            for (int k = 0; k < NA; k++) a1[k] += av[k];
        } else if (t == 2) {
            int idx = (int)av[0];
            idx = idx < 0 ? 0 : (idx > NA - 1 ? NA - 1 : idx);
            #pragma unroll
            for (int k = 0; k < NA; k++) c2[k] += (k == idx) ? 1.f : 0.f;
        }
    }

    __shared__ float s_acc[56];
    for (int j = threadIdx.x; j < 56; j += blockDim.x) s_acc[j] = 0.f;
    __syncthreads();

    int lane = threadIdx.x & 31;
    #pragma unroll
    for (int k = 0; k < NA; k++) {
        float v = a0[k];
        #pragma unroll
        for (int o = 16; o; o >>= 1) v += __shfl_xor_sync(0xffffffffu, v, o);
        if (lane == 0) atomicAdd(&s_acc[k], v);
        v = a1[k];
        #pragma unroll
        for (int o = 16; o; o >>= 1) v += __shfl_xor_sync(0xffffffffu, v, o);
        if (lane == 0) atomicAdd(&s_acc[NA + k], v);
        v = c2[k];
        #pragma unroll
        for (int o = 16; o; o >>= 1) v += __shfl_xor_sync(0xffffffffu, v, o);
        if (lane == 0) atomicAdd(&s_acc[2 * NA + k], v);
    }
    {
        float v = n0;
        #pragma unroll
        for (int o = 16; o; o >>= 1) v += __shfl_xor_sync(0xffffffffu, v, o);
        if (lane == 0) atomicAdd(&s_acc[51], v);
        v = n1;
        #pragma unroll
        for (int o = 16; o; o >>= 1) v += __shfl_xor_sync(0xffffffffu, v, o);
        if (lane == 0) atomicAdd(&s_acc[52], v);
    }
    __syncthreads();
    for (int j = threadIdx.x; j < 56; j += blockDim.x) d_stats[gph * 56 + j] = s_acc[j];
}

// ---------------- K3: segment sum of x + fused tiny emb GEMM + mean ----------
// (round-2 version: one block per graph, 256 threads)
__global__ void k_pool(const float* __restrict__ x,
                       const float* __restrict__ netW, const float* __restrict__ netb,
                       const float* __restrict__ devW, const float* __restrict__ devb,
                       const float* __restrict__ pinE) {
    int gph = blockIdx.x;
    int s0 = d_starts[gph], s1 = d_starts[gph + 1];

    __shared__ float st[56];
    for (int j = threadIdx.x; j < 56; j += 256) st[j] = d_stats[gph * 56 + j];
    __syncthreads();

    int c4 = threadIdx.x;
    const float4* x4 = (const float4*)x;
    float4 acc = make_float4(0.f, 0.f, 0.f, 0.f);

    #pragma unroll 4
    for (int r = s0; r < s1; r++) {
        float4 v = x4[(long)r * 256 + c4];
        acc.x += v.x; acc.y += v.y; acc.z += v.z; acc.w += v.w;
    }

    const float4* nW4 = (const float4*)netW;
    const float4* dW4 = (const float4*)devW;
    const float4* pE4 = (const float4*)pinE;
    float4 e = make_float4(0.f, 0.f, 0.f, 0.f);
    #pragma unroll
    for (int k = 0; k < NA; k++) {
        float4 wn = nW4[k * 256 + c4];
        float4 wd = dW4[k * 256 + c4];
        float4 wp = pE4[k * 256 + c4];
        float a0 = st[k], a1 = st[NA + k], cc = st[2 * NA + k];
        e.x += a0 * wn.x + a1 * wd.x + cc * wp.x;
        e.y += a0 * wn.y + a1 * wd.y + cc * wp.y;
        e.z += a0 * wn.z + a1 * wd.z + cc * wp.z;
        e.w += a0 * wn.w + a1 * wd.w + cc * wp.w;
    }
    float n0 = st[51], n1 = st[52];
    float4 nb = ((const float4*)netb)[c4];
    float4 db = ((const float4*)devb)[c4];
    e.x += n0 * nb.x + n1 * db.x;
    e.y += n0 * nb.y + n1 * db.y;
    e.z += n0 * nb.z + n1 * db.z;
    e.w += n0 * nb.w + n1 * db.w;

    float inv = 1.f / fmaxf((float)(s1 - s0), 1.f);
    float4 o;
    o.x = (acc.x + e.x) * inv;
    o.y = (acc.y + e.y) * inv;
    o.z = (acc.z + e.z) * inv;
    o.w = (acc.w + e.w) * inv;
    ((float4*)d_pooled)[(long)gph * 256 + c4] = o;
}

// ---------------- K4: split-K GEMM, 128x128 tile, 8x8/thread, f32x2 packed ----
// B stored duplicated {w,w} in smem so inner loop is LDS.128 + fma.rn.f32x2 only.
template<int SPLIT>
__global__ void k_gemm(const float* __restrict__ A, const float* __restrict__ W,
                       float* __restrict__ part, int M, int N, int K) {
    const int kChunk = K / SPLIT;
    __shared__ float As[16][128];
    __shared__ unsigned long long Bs[16][128];

    int tid = threadIdx.x;
    int tx = tid & 15;        // col group: 8 cols
    int ty = tid >> 4;        // row group: 8 rows
    int n0 = blockIdx.x * 128, m0 = blockIdx.y * 128;
    int k0 = blockIdx.z * kChunk, kend = k0 + kChunk;

    unsigned long long acc[4][8];
    #pragma unroll
    for (int p = 0; p < 4; p++)
        #pragma unroll
        for (int j = 0; j < 8; j++) acc[p][j] = 0ull;

    int am[8], ak[8], bkk[8], bn[8];
    #pragma unroll
    for (int i = 0; i < 8; i++) {
        int idx = tid + i * 256;
        am[i] = idx >> 4;  ak[i] = idx & 15;     // A: 128 rows x 16 k
        bkk[i] = idx >> 7; bn[i] = idx & 127;    // B: 16 k x 128 n
    }

    float ra[8], rbv[8];
    #pragma unroll
    for (int i = 0; i < 8; i++) ra[i] = A[(long)(m0 + am[i]) * K + k0 + ak[i]];
    #pragma unroll
    for (int i = 0; i < 8; i++) rbv[i] = W[(long)(k0 + bkk[i]) * N + n0 + bn[i]];

    for (int kb = k0; kb < kend; kb += 16) {
        #pragma unroll
        for (int i = 0; i < 8; i++) As[ak[i]][am[i]] = ra[i];
        #pragma unroll
        for (int i = 0; i < 8; i++) Bs[bkk[i]][bn[i]] = pack2(rbv[i], rbv[i]);
        __syncthreads();

        int kn = kb + 16;
        if (kn < kend) {
            #pragma unroll
            for (int i = 0; i < 8; i++) ra[i] = A[(long)(m0 + am[i]) * K + kn + ak[i]];
            #pragma unroll
            for (int i = 0; i < 8; i++) rbv[i] = W[(long)(kn + bkk[i]) * N + n0 + bn[i]];
        }

        #pragma unroll
        for (int kk = 0; kk < 16; kk++) {
            ulonglong2 a01 = *(const ulonglong2*)&As[kk][ty * 8];
            ulonglong2 a23 = *(const ulonglong2*)&As[kk][ty * 8 + 4];
            unsigned long long ap[4] = {a01.x, a01.y, a23.x, a23.y};
            ulonglong2 b0 = *(const ulonglong2*)&Bs[kk][tx * 8];
            ulonglong2 b1 = *(const ulonglong2*)&Bs[kk][tx * 8 + 2];
            ulonglong2 b2 = *(const ulonglong2*)&Bs[kk][tx * 8 + 4];
            ulonglong2 b3 = *(const ulonglong2*)&Bs[kk][tx * 8 + 6];
            unsigned long long bp[8] = {b0.x, b0.y, b1.x, b1.y, b2.x, b2.y, b3.x, b3.y};
            #pragma unroll
            for (int p = 0; p < 4; p++)
                #pragma unroll
                for (int j = 0; j < 8; j++)
                    FMA2(acc[p][j], ap[p], bp[j]);
        }
        __syncthreads();
    }

    float* dst = part + (long)blockIdx.z * M * N;
    int c0 = n0 + tx * 8;
    #pragma unroll
    for (int p = 0; p < 4; p++) {
        int r0 = m0 + ty * 8 + 2 * p;
        float lo[8], hi[8];
        #pragma unroll
        for (int j = 0; j < 8; j++) unpack2(acc[p][j], lo[j], hi[j]);
        *(float4*)&dst[(long)r0 * N + c0]     = make_float4(lo[0], lo[1], lo[2], lo[3]);
        *(float4*)&dst[(long)r0 * N + c0 + 4] = make_float4(lo[4], lo[5], lo[6], lo[7]);
        *(float4*)&dst[(long)(r0 + 1) * N + c0]     = make_float4(hi[0], hi[1], hi[2], hi[3]);
        *(float4*)&dst[(long)(r0 + 1) * N + c0 + 4] = make_float4(hi[4], hi[5], hi[6], hi[7]);
    }
}

// ---------------- K5: combine split-K + bias + relu + column stats -----------
template<int SPLIT>
__global__ void k_combine_stats(const float* __restrict__ part, const float* __restrict__ bias,
                                float* __restrict__ out, int MN, int N) {
    int tx = threadIdx.x & 15;
    int ty = threadIdx.x >> 4;
    int c4 = blockIdx.x * 16 + tx;
    int rbase = blockIdx.y * 128;
    int N4 = N >> 2;

    float4 bb = ((const float4*)bias)[c4];
    float4 sum = make_float4(0.f, 0.f, 0.f, 0.f);
    float4 sq  = make_float4(0.f, 0.f, 0.f, 0.f);

    for (int r = rbase + ty; r < rbase + 128; r += 16) {
        float4 v = make_float4(0.f, 0.f, 0.f, 0.f);
        long base = (long)r * N4 + c4;
        #pragma unroll
        for (int s = 0; s < SPLIT; s++) {
            float4 p = ((const float4*)part)[(long)s * (MN >> 2) + base];
            v.x += p.x; v.y += p.y; v.z += p.z; v.w += p.w;
        }
        v.x = fmaxf(v.x + bb.x, 0.f);
        v.y = fmaxf(v.y + bb.y, 0.f);
        v.z = fmaxf(v.z + bb.z, 0.f);
        v.w = fmaxf(v.w + bb.w, 0.f);
        ((float4*)out)[base] = v;
        sum.x += v.x; sum.y += v.y; sum.z += v.z; sum.w += v.w;
        sq.x += v.x * v.x; sq.y += v.y * v.y; sq.z += v.z * v.z; sq.w += v.w * v.w;
    }

    __shared__ float4 ssum[16][16], ssq[16][16];
    ssum[ty][tx] = sum; ssq[ty][tx] = sq;
    __syncthreads();
    if (ty == 0) {
        float4 S = ssum[0][tx], Q = ssq[0][tx];
        #pragma unroll
        for (int j = 1; j < 16; j++) {
            float4 s2 = ssum[j][tx], q2 = ssq[j][tx];
            S.x += s2.x; S.y += s2.y; S.z += s2.z; S.w += s2.w;
            Q.x += q2.x; Q.y += q2.y; Q.z += q2.z; Q.w += q2.w;
        }
        int col = c4 * 4;
        *(float4*)&d_bnsum[blockIdx.y * N + col] = S;
        *(float4*)&d_bnsq[blockIdx.y * N + col] = Q;
    }
}

// ---------------- K6: finalize BN -> scale/shift ------------------------------
__global__ void k_bnfinal(const float* __restrict__ g, const float* __restrict__ b, int N) {
    int c = blockIdx.x * blockDim.x + threadIdx.x;
    if (c >= N) return;
    float s = 0.f, q = 0.f;
    #pragma unroll
    for (int ch = 0; ch < 8; ch++) { s += d_bnsum[ch * N + c]; q += d_bnsq[ch * N + c]; }
    float m = s / (float)GG;
    float var = q / (float)GG - m * m;
    float rs = rsqrtf(var + EPS);
    float sc = rs * g[c];
    d_scale[c] = sc;
    d_shift[c] = b[c] - m * sc;
}

// ---------------- K6b: fold BN0 into fc1 weights ------------------------------
__global__ void k_foldW1(const float* __restrict__ W1) {
    int i = blockIdx.x * 256 + threadIdx.x;     // 512*256 elems
    int k = i >> 8;
    d_w1p[i] = W1[i] * d_scale[k];
}
__global__ void k_foldb1(const float* __restrict__ W1, const float* __restrict__ b1) {
    int n = threadIdx.x;                         // 256
    float s = b1[n];
    #pragma unroll 4
    for (int k = 0; k < DD / 2; k++) s += d_shift[k] * W1[k * (DD / 4) + n];
    d_b1p[n] = s;
}

// ---------------- K7: fc2 dot(256) with fused BN1 + output assembly ----------
__global__ void k_head_out(const float* __restrict__ R1, const float* __restrict__ w,
                           const float* __restrict__ b, const float* __restrict__ y_reg,
                           float* __restrict__ out, int out_size) {
    int warp = (blockIdx.x * blockDim.x + threadIdx.x) >> 5;
    int lane = threadIdx.x & 31;
    if (warp >= GG) return;
    float s = 0.f;
    #pragma unroll
    for (int k = lane; k < DD / 4; k += 32) {
        float h = R1[(long)warp * (DD / 4) + k] * d_scale[k] + d_shift[k];
        s += h * w[k];
    }
    #pragma unroll
    for (int o = 16; o; o >>= 1) s += __shfl_xor_sync(0xffffffffu, s, o);
    if (lane == 0) {
        out[warp] = s + b[0];
        if (out_size >= 2 * GG) out[GG + warp] = y_reg[warp];
    }
}

// ---------------- launch ------------------------------------------------------
extern "C" void kernel_launch(void* const* d_in, const int* in_sizes, int n_in,
                              void* d_out, int out_size) {
    const float* x        = (const float*)d_in[0];
    const float* nattr    = (const float*)d_in[1];
    const int*   ntype    = (const int*)d_in[2];
    const int*   batch    = (const int*)d_in[3];
    const float* y_reg    = (const float*)d_in[4];
    const float* net_W    = (const float*)d_in[5];
    const float* net_b    = (const float*)d_in[6];
    const float* dev_W    = (const float*)d_in[7];
    const float* dev_b    = (const float*)d_in[8];
    const float* pin_emb  = (const float*)d_in[9];
    const float* fc0_W    = (const float*)d_in[10];
    const float* fc0_b    = (const float*)d_in[11];
    const float* fc1_W    = (const float*)d_in[12];
    const float* fc1_b    = (const float*)d_in[13];
    const float* fc2_W    = (const float*)d_in[14];
    const float* fc2_b    = (const float*)d_in[15];
    const float* bn0_g    = (const float*)d_in[16];
    const float* bn0_b    = (const float*)d_in[17];
    const float* bn1_g    = (const float*)d_in[18];
    const float* bn1_b    = (const float*)d_in[19];
    float* out = (float*)d_out;

    float *p_pooled, *p_part, *p_r0, *p_r1, *p_w1p, *p_b1p;
    cudaGetSymbolAddress((void**)&p_pooled, d_pooled);
    cudaGetSymbolAddress((void**)&p_part, d_part);
    cudaGetSymbolAddress((void**)&p_r0, d_r0);
    cudaGetSymbolAddress((void**)&p_r1, d_r1);
    cudaGetSymbolAddress((void**)&p_w1p, d_w1p);
    cudaGetSymbolAddress((void**)&p_b1p, d_b1p);

    const int N0 = DD / 2;   // 512
    const int N1 = DD / 4;   // 256
    const int MN0 = GG * N0;
    const int MN1 = GG * N1;

    k_find_starts<<<(GG + 1 + 255) / 256, 256>>>(batch);
    k_stats<<<GG, 128>>>(nattr, ntype);
    k_pool<<<GG, 256>>>(x, net_W, net_b, dev_W, dev_b, pin_emb);

    // fc0: 1024x512x1024, split-K 8 -> 4x8x8 = 256 blocks
    k_gemm<8><<<dim3(N0 / 128, GG / 128, 8), 256>>>(p_pooled, fc0_W, p_part, GG, N0, DD);
    k_combine_stats<8><<<dim3(N0 / 64, 8), 256>>>(p_part, fc0_b, p_r0, MN0, N0);
    k_bnfinal<<<(N0 + 255) / 256, 256>>>(bn0_g, bn0_b, N0);
    k_foldW1<<<(N0 * N1) / 256, 256>>>(fc1_W);
    k_foldb1<<<1, N1>>>(fc1_W, fc1_b);

    // fc1: 1024x256x512 on folded weights, split-K 16 -> 2x8x16 = 256 blocks
    k_gemm<16><<<dim3(N1 / 128, GG / 128, 16), 256>>>(p_r0, p_w1p, p_part, GG, N1, N0);
    k_combine_stats<16><<<dim3(N1 / 64, 8), 256>>>(p_part, p_b1p, p_r1, MN1, N1);
    k_bnfinal<<<(N1 + 255) / 256, 256>>>(bn1_g, bn1_b, N1);

    k_head_out<<<(GG * 32 + 255) / 256, 256>>>(p_r1, fc2_W, fc2_b, y_reg, out, out_size);
}

// round 5
// speedup vs baseline: 1.3314x; 1.3314x over previous
#include <cuda_runtime.h>
#include <cuda_bf16.h>

#define NN 262144
#define DD 1024
#define GG 1024
#define NA 17
#define EPS 1e-5f

// ---------------- scratch (device globals; no allocation allowed) -------------
__device__ int   d_starts[GG + 1];
__device__ float d_stats[GG * 56];
__device__ float d_pooled[GG * DD];                // 4 MB
__device__ float d_part[4 * 1024 * 1024];          // 16 MB split-K partials (reused)
__device__ float d_r0[GG * (DD / 2)];
__device__ float d_r1[GG * (DD / 4)];
__device__ float d_bnsum[8 * (DD / 2)];
__device__ float d_bnsq[8 * (DD / 2)];
__device__ float d_scale[DD / 2];
__device__ float d_shift[DD / 2];
__device__ float d_w1p[(DD / 2) * (DD / 4)];       // scale-folded fc1_W
__device__ float d_b1pp[8][DD / 4];                // partial shift-dot
__device__ float d_b1p[DD / 4];                    // shift-folded fc1 bias

// ---------------- K1: segment starts ------------------------------------------
__global__ void k_find_starts(const int* __restrict__ batch) {
    int i = blockIdx.x * blockDim.x + threadIdx.x;
    if (i > GG) return;
    int lo = 0, hi = NN;
    while (lo < hi) {
        int mid = (lo + hi) >> 1;
        if (batch[mid] < i) lo = mid + 1; else hi = mid;
    }
    d_starts[i] = lo;
}

// ---------------- K2: per-graph attr stats (smem-staged, coalesced) -----------
__global__ void k_stats(const float* __restrict__ attr, const int* __restrict__ ntype) {
    int gph = blockIdx.x;
    int s0 = d_starts[gph], s1 = d_starts[gph + 1];

    __shared__ float sa[128 * NA];   // 2176 floats

    float a0[NA], a1[NA], c2[NA];
    #pragma unroll
    for (int k = 0; k < NA; k++) { a0[k] = 0.f; a1[k] = 0.f; c2[k] = 0.f; }
    float n0 = 0.f, n1 = 0.f;

    for (int base = s0; base < s1; base += 128) {
        int nrows = min(128, s1 - base);
        int nf = nrows * NA;
        __syncthreads();
        for (int j = threadIdx.x; j < nf; j += 128)
            sa[j] = attr[(long)base * NA + j];
        __syncthreads();
        if ((int)threadIdx.x < nrows) {
            int t = ntype[base + threadIdx.x];
            const float* ar = &sa[threadIdx.x * NA];
            if (t == 0) {
                n0 += 1.f;
                #pragma unroll
                for (int k = 0; k < NA; k++) a0[k] += ar[k];
            } else if (t == 1) {
                n1 += 1.f;
                #pragma unroll
                for (int k = 0; k < NA; k++) a1[k] += ar[k];
            } else if (t == 2) {
                int idx = (int)ar[0];
                idx = idx < 0 ? 0 : (idx > NA - 1 ? NA - 1 : idx);
                #pragma unroll
                for (int k = 0; k < NA; k++) c2[k] += (k == idx) ? 1.f : 0.f;
            }
        }
    }

    __shared__ float s_acc[56];
    __syncthreads();
    for (int j = threadIdx.x; j < 56; j += 128) s_acc[j] = 0.f;
    __syncthreads();

    int lane = threadIdx.x & 31;
    #pragma unroll
    for (int k = 0; k < NA; k++) {
        float v = a0[k];
        #pragma unroll
        for (int o = 16; o; o >>= 1) v += __shfl_xor_sync(0xffffffffu, v, o);
        if (lane == 0) atomicAdd(&s_acc[k], v);
        v = a1[k];
        #pragma unroll
        for (int o = 16; o; o >>= 1) v += __shfl_xor_sync(0xffffffffu, v, o);
        if (lane == 0) atomicAdd(&s_acc[NA + k], v);
        v = c2[k];
        #pragma unroll
        for (int o = 16; o; o >>= 1) v += __shfl_xor_sync(0xffffffffu, v, o);
        if (lane == 0) atomicAdd(&s_acc[2 * NA + k], v);
    }
    {
        float v = n0;
        #pragma unroll
        for (int o = 16; o; o >>= 1) v += __shfl_xor_sync(0xffffffffu, v, o);
        if (lane == 0) atomicAdd(&s_acc[51], v);
        v = n1;
        #pragma unroll
        for (int o = 16; o; o >>= 1) v += __shfl_xor_sync(0xffffffffu, v, o);
        if (lane == 0) atomicAdd(&s_acc[52], v);
    }
    __syncthreads();
    for (int j = threadIdx.x; j < 56; j += 128) d_stats[gph * 56 + j] = s_acc[j];
}

// ---------------- K3: segment sum of x + fused tiny emb GEMM + mean ----------
__global__ void k_pool(const float* __restrict__ x,
                       const float* __restrict__ netW, const float* __restrict__ netb,
                       const float* __restrict__ devW, const float* __restrict__ devb,
                       const float* __restrict__ pinE) {
    int gph = blockIdx.x;
    int s0 = d_starts[gph], s1 = d_starts[gph + 1];

    __shared__ float st[56];
    for (int j = threadIdx.x; j < 56; j += 256) st[j] = d_stats[gph * 56 + j];
    __syncthreads();

    int c4 = threadIdx.x;
    const float4* x4 = (const float4*)x;
    float4 acc = make_float4(0.f, 0.f, 0.f, 0.f);

    #pragma unroll 4
    for (int r = s0; r < s1; r++) {
        float4 v = x4[(long)r * 256 + c4];
        acc.x += v.x; acc.y += v.y; acc.z += v.z; acc.w += v.w;
    }

    const float4* nW4 = (const float4*)netW;
    const float4* dW4 = (const float4*)devW;
    const float4* pE4 = (const float4*)pinE;
    float4 e = make_float4(0.f, 0.f, 0.f, 0.f);
    #pragma unroll
    for (int k = 0; k < NA; k++) {
        float4 wn = nW4[k * 256 + c4];
        float4 wd = dW4[k * 256 + c4];
        float4 wp = pE4[k * 256 + c4];
        float a0 = st[k], a1 = st[NA + k], cc = st[2 * NA + k];
        e.x += a0 * wn.x + a1 * wd.x + cc * wp.x;
        e.y += a0 * wn.y + a1 * wd.y + cc * wp.y;
        e.z += a0 * wn.z + a1 * wd.z + cc * wp.z;
        e.w += a0 * wn.w + a1 * wd.w + cc * wp.w;
    }
    float n0 = st[51], n1 = st[52];
    float4 nb = ((const float4*)netb)[c4];
    float4 db = ((const float4*)devb)[c4];
    e.x += n0 * nb.x + n1 * db.x;
    e.y += n0 * nb.y + n1 * db.y;
    e.z += n0 * nb.z + n1 * db.z;
    e.w += n0 * nb.w + n1 * db.w;

    float inv = 1.f / fmaxf((float)(s1 - s0), 1.f);
    float4 o;
    o.x = (acc.x + e.x) * inv;
    o.y = (acc.y + e.y) * inv;
    o.z = (acc.z + e.z) * inv;
    o.w = (acc.w + e.w) * inv;
    ((float4*)d_pooled)[(long)gph * 256 + c4] = o;
}

// ---------------- K4: split-K GEMM, 128x64 tile, 8x4/thread (proven R2/R3) ---
__global__ void k_gemm_splitk(const float* __restrict__ A, const float* __restrict__ W,
                              float* __restrict__ part, int M, int N, int K, int kChunk) {
    __shared__ float As[16][128];
    __shared__ float Bs[16][68];
    int tid = threadIdx.x;
    int tx = tid & 15;
    int ty = tid >> 4;
    int n0 = blockIdx.x * 64, m0 = blockIdx.y * 128;
    int k0 = blockIdx.z * kChunk;
    float acc[8][4] = {};

    for (int kb = k0; kb < k0 + kChunk; kb += 16) {
        #pragma unroll
        for (int i = 0; i < 8; i++) {
            int idx = tid + i * 256;
            int m = idx >> 4, kk = idx & 15;
            As[kk][m] = A[(long)(m0 + m) * K + kb + kk];
        }
        #pragma unroll
        for (int i = 0; i < 4; i++) {
            int idx = tid + i * 256;
            int kk = idx >> 6, n = idx & 63;
            Bs[kk][n] = W[(long)(kb + kk) * N + n0 + n];
        }
        __syncthreads();
        #pragma unroll
        for (int kk = 0; kk < 16; kk++) {
            float4 a0 = *(const float4*)&As[kk][ty * 8];
            float4 a1 = *(const float4*)&As[kk][ty * 8 + 4];
            float4 b  = *(const float4*)&Bs[kk][tx * 4];
            float av[8] = {a0.x, a0.y, a0.z, a0.w, a1.x, a1.y, a1.z, a1.w};
            float bv[4] = {b.x, b.y, b.z, b.w};
            #pragma unroll
            for (int i = 0; i < 8; i++)
                #pragma unroll
                for (int j = 0; j < 4; j++)
                    acc[i][j] += av[i] * bv[j];
        }
        __syncthreads();
    }
    float* dst = part + (long)blockIdx.z * M * N;
    #pragma unroll
    for (int i = 0; i < 8; i++) {
        int m = m0 + ty * 8 + i;
        #pragma unroll
        for (int j = 0; j < 4; j++)
            dst[(long)m * N + n0 + tx * 4 + j] = acc[i][j];
    }
}

// ---------------- K5: combine split-K + bias + relu + column stats -----------
template<int SPLIT>
__global__ void k_combine_stats(const float* __restrict__ part, const float* __restrict__ bias,
                                float* __restrict__ out, int MN, int N) {
    int tx = threadIdx.x & 15;
    int ty = threadIdx.x >> 4;
    int c4 = blockIdx.x * 16 + tx;
    int rbase = blockIdx.y * 128;
    int N4 = N >> 2;

    float4 bb = ((const float4*)bias)[c4];
    float4 sum = make_float4(0.f, 0.f, 0.f, 0.f);
    float4 sq  = make_float4(0.f, 0.f, 0.f, 0.f);

    for (int r = rbase + ty; r < rbase + 128; r += 16) {
        float4 v = make_float4(0.f, 0.f, 0.f, 0.f);
        long base = (long)r * N4 + c4;
        #pragma unroll
        for (int s = 0; s < SPLIT; s++) {
            float4 p = ((const float4*)part)[(long)s * (MN >> 2) + base];
            v.x += p.x; v.y += p.y; v.z += p.z; v.w += p.w;
        }
        v.x = fmaxf(v.x + bb.x, 0.f);
        v.y = fmaxf(v.y + bb.y, 0.f);
        v.z = fmaxf(v.z + bb.z, 0.f);
        v.w = fmaxf(v.w + bb.w, 0.f);
        ((float4*)out)[base] = v;
        sum.x += v.x; sum.y += v.y; sum.z += v.z; sum.w += v.w;
        sq.x += v.x * v.x; sq.y += v.y * v.y; sq.z += v.z * v.z; sq.w += v.w * v.w;
    }

    __shared__ float4 ssum[16][16], ssq[16][16];
    ssum[ty][tx] = sum; ssq[ty][tx] = sq;
    __syncthreads();
    if (ty == 0) {
        float4 S = ssum[0][tx], Q = ssq[0][tx];
        #pragma unroll
        for (int j = 1; j < 16; j++) {
            float4 s2 = ssum[j][tx], q2 = ssq[j][tx];
            S.x += s2.x; S.y += s2.y; S.z += s2.z; S.w += s2.w;
            Q.x += q2.x; Q.y += q2.y; Q.z += q2.z; Q.w += q2.w;
        }
        int col = c4 * 4;
        *(float4*)&d_bnsum[blockIdx.y * N + col] = S;
        *(float4*)&d_bnsq[blockIdx.y * N + col] = Q;
    }
}

// ---------------- K6: finalize BN -> scale/shift ------------------------------
__global__ void k_bnfinal(const float* __restrict__ g, const float* __restrict__ b, int N) {
    int c = blockIdx.x * blockDim.x + threadIdx.x;
    if (c >= N) return;
    float s = 0.f, q = 0.f;
    #pragma unroll
    for (int ch = 0; ch < 8; ch++) { s += d_bnsum[ch * N + c]; q += d_bnsq[ch * N + c]; }
    float m = s / (float)GG;
    float var = q / (float)GG - m * m;
    float rs = rsqrtf(var + EPS);
    float sc = rs * g[c];
    d_scale[c] = sc;
    d_shift[c] = b[c] - m * sc;
}

// ---------------- K6b: fold BN0 into fc1 weights ------------------------------
__global__ void k_foldW1(const float* __restrict__ W1) {
    int i = blockIdx.x * 256 + threadIdx.x;     // 512*256 elems
    int k = i >> 8;
    d_w1p[i] = W1[i] * d_scale[k];
}
// partial shift-dot: 8 blocks, block b covers k in [b*64,(b+1)*64)
__global__ void k_foldb1a(const float* __restrict__ W1) {
    int b = blockIdx.x;
    int n = threadIdx.x & 255;
    // 256 threads: each handles one n over 64 k values (coalesced along n)
    float s = 0.f;
    int kbase = b * 64;
    #pragma unroll 8
    for (int k = 0; k < 64; k++)
        s += d_shift[kbase + k] * W1[(long)(kbase + k) * (DD / 4) + n];
    d_b1pp[b][n] = s;
}
__global__ void k_foldb1b(const float* __restrict__ b1) {
    int n = threadIdx.x;
    float s = b1[n];
    #pragma unroll
    for (int b = 0; b < 8; b++) s += d_b1pp[b][n];
    d_b1p[n] = s;
}

// ---------------- K7: fc2 dot(256) with fused BN1 + output assembly ----------
__global__ void k_head_out(const float* __restrict__ R1, const float* __restrict__ w,
                           const float* __restrict__ b, const float* __restrict__ y_reg,
                           float* __restrict__ out, int out_size) {
    int warp = (blockIdx.x * blockDim.x + threadIdx.x) >> 5;
    int lane = threadIdx.x & 31;
    if (warp >= GG) return;
    float s = 0.f;
    #pragma unroll
    for (int k = lane; k < DD / 4; k += 32) {
        float h = R1[(long)warp * (DD / 4) + k] * d_scale[k] + d_shift[k];
        s += h * w[k];
    }
    #pragma unroll
    for (int o = 16; o; o >>= 1) s += __shfl_xor_sync(0xffffffffu, s, o);
    if (lane == 0) {
        out[warp] = s + b[0];
        if (out_size >= 2 * GG) out[GG + warp] = y_reg[warp];
    }
}

// ---------------- launch ------------------------------------------------------
extern "C" void kernel_launch(void* const* d_in, const int* in_sizes, int n_in,
                              void* d_out, int out_size) {
    const float* x        = (const float*)d_in[0];
    const float* nattr    = (const float*)d_in[1];
    const int*   ntype    = (const int*)d_in[2];
    const int*   batch    = (const int*)d_in[3];
    const float* y_reg    = (const float*)d_in[4];
    const float* net_W    = (const float*)d_in[5];
    const float* net_b    = (const float*)d_in[6];
    const float* dev_W    = (const float*)d_in[7];
    const float* dev_b    = (const float*)d_in[8];
    const float* pin_emb  = (const float*)d_in[9];
    const float* fc0_W    = (const float*)d_in[10];
    const float* fc0_b    = (const float*)d_in[11];
    const float* fc1_W    = (const float*)d_in[12];
    const float* fc1_b    = (const float*)d_in[13];
    const float* fc2_W    = (const float*)d_in[14];
    const float* fc2_b    = (const float*)d_in[15];
    const float* bn0_g    = (const float*)d_in[16];
    const float* bn0_b    = (const float*)d_in[17];
    const float* bn1_g    = (const float*)d_in[18];
    const float* bn1_b    = (const float*)d_in[19];
    float* out = (float*)d_out;

    float *p_pooled, *p_part, *p_r0, *p_r1, *p_w1p, *p_b1p;
    cudaGetSymbolAddress((void**)&p_pooled, d_pooled);
    cudaGetSymbolAddress((void**)&p_part, d_part);
    cudaGetSymbolAddress((void**)&p_r0, d_r0);
    cudaGetSymbolAddress((void**)&p_r1, d_r1);
    cudaGetSymbolAddress((void**)&p_w1p, d_w1p);
    cudaGetSymbolAddress((void**)&p_b1p, d_b1p);

    const int N0 = DD / 2;   // 512
    const int N1 = DD / 4;   // 256
    const int MN0 = GG * N0;
    const int MN1 = GG * N1;

    k_find_starts<<<(GG + 1 + 255) / 256, 256>>>(batch);
    k_stats<<<GG, 128>>>(nattr, ntype);
    k_pool<<<GG, 256>>>(x, net_W, net_b, dev_W, dev_b, pin_emb);

    // fc0: 1024x512x1024, split-K 8 -> 8x8x8 = 512 blocks (R3-measured 49.8us)
    k_gemm_splitk<<<dim3(N0 / 64, GG / 128, 8), 256>>>(p_pooled, fc0_W, p_part, GG, N0, DD, DD / 8);
    k_combine_stats<8><<<dim3(N0 / 64, 8), 256>>>(p_part, fc0_b, p_r0, MN0, N0);
    k_bnfinal<<<(N0 + 255) / 256, 256>>>(bn0_g, bn0_b, N0);
    k_foldW1<<<(N0 * N1) / 256, 256>>>(fc1_W);
    k_foldb1a<<<8, 256>>>(fc1_W);
    k_foldb1b<<<1, N1>>>(fc1_b);

    // fc1: 1024x256x512 on folded weights, split-K 8 -> 4x8x8 = 256 blocks
    k_gemm_splitk<<<dim3(N1 / 64, GG / 128, 8), 256>>>(p_r0, p_w1p, p_part, GG, N1, N0, N0 / 8);
    k_combine_stats<8><<<dim3(N1 / 64, 8), 256>>>(p_part, p_b1p, p_r1, MN1, N1);
    k_bnfinal<<<(N1 + 255) / 256, 256>>>(bn1_g, bn1_b, N1);

    k_head_out<<<(GG * 32 + 255) / 256, 256>>>(p_r1, fc2_W, fc2_b, y_reg, out, out_size);
}

// round 6
// speedup vs baseline: 1.3792x; 1.0359x over previous
#include <cuda_runtime.h>
#include <cuda_bf16.h>

#define NN 262144
#define DD 1024
#define GG 1024
#define NA 17
#define EPS 1e-5f

// ---------------- scratch (device globals; no allocation allowed) -------------
__device__ int   d_starts[GG + 1];
__device__ float d_stats[GG * 56];
__device__ float d_pooled[GG * DD];                // 4 MB
__device__ float d_part[4 * 1024 * 1024];          // 16 MB split-K partials (reused)
__device__ float d_r0[GG * (DD / 2)];
__device__ float d_r1[GG * (DD / 4)];
__device__ float d_bnsum[8 * (DD / 2)];
__device__ float d_bnsq[8 * (DD / 2)];
__device__ float d_scale[DD / 2];
__device__ float d_shift[DD / 2];
__device__ float d_w1p[(DD / 2) * (DD / 4)];       // scale-folded fc1_W
__device__ float d_b1pp[8][DD / 4];                // partial shift-dot
__device__ float d_b1p[DD / 4];                    // shift-folded fc1 bias

// ---------------- K1: segment starts ------------------------------------------
__global__ void k_find_starts(const int* __restrict__ batch) {
    int i = blockIdx.x * blockDim.x + threadIdx.x;
    if (i > GG) return;
    int lo = 0, hi = NN;
    while (lo < hi) {
        int mid = (lo + hi) >> 1;
        if (batch[mid] < i) lo = mid + 1; else hi = mid;
    }
    d_starts[i] = lo;
}

// ---------------- K2: per-graph attr stats (smem-staged, coalesced) -----------
__global__ void k_stats(const float* __restrict__ attr, const int* __restrict__ ntype) {
    int gph = blockIdx.x;
    int s0 = d_starts[gph], s1 = d_starts[gph + 1];

    __shared__ float sa[128 * NA];

    float a0[NA], a1[NA], c2[NA];
    #pragma unroll
    for (int k = 0; k < NA; k++) { a0[k] = 0.f; a1[k] = 0.f; c2[k] = 0.f; }
    float n0 = 0.f, n1 = 0.f;

    for (int base = s0; base < s1; base += 128) {
        int nrows = min(128, s1 - base);
        int nf = nrows * NA;
        __syncthreads();
        for (int j = threadIdx.x; j < nf; j += 128)
            sa[j] = attr[(long)base * NA + j];
        __syncthreads();
        if ((int)threadIdx.x < nrows) {
            int t = ntype[base + threadIdx.x];
            const float* ar = &sa[threadIdx.x * NA];
            if (t == 0) {
                n0 += 1.f;
                #pragma unroll
                for (int k = 0; k < NA; k++) a0[k] += ar[k];
            } else if (t == 1) {
                n1 += 1.f;
                #pragma unroll
                for (int k = 0; k < NA; k++) a1[k] += ar[k];
            } else if (t == 2) {
                int idx = (int)ar[0];
                idx = idx < 0 ? 0 : (idx > NA - 1 ? NA - 1 : idx);
                #pragma unroll
                for (int k = 0; k < NA; k++) c2[k] += (k == idx) ? 1.f : 0.f;
            }
        }
    }

    __shared__ float s_acc[56];
    __syncthreads();
    for (int j = threadIdx.x; j < 56; j += 128) s_acc[j] = 0.f;
    __syncthreads();

    int lane = threadIdx.x & 31;
    #pragma unroll
    for (int k = 0; k < NA; k++) {
        float v = a0[k];
        #pragma unroll
        for (int o = 16; o; o >>= 1) v += __shfl_xor_sync(0xffffffffu, v, o);
        if (lane == 0) atomicAdd(&s_acc[k], v);
        v = a1[k];
        #pragma unroll
        for (int o = 16; o; o >>= 1) v += __shfl_xor_sync(0xffffffffu, v, o);
        if (lane == 0) atomicAdd(&s_acc[NA + k], v);
        v = c2[k];
        #pragma unroll
        for (int o = 16; o; o >>= 1) v += __shfl_xor_sync(0xffffffffu, v, o);
        if (lane == 0) atomicAdd(&s_acc[2 * NA + k], v);
    }
    {
        float v = n0;
        #pragma unroll
        for (int o = 16; o; o >>= 1) v += __shfl_xor_sync(0xffffffffu, v, o);
        if (lane == 0) atomicAdd(&s_acc[51], v);
        v = n1;
        #pragma unroll
        for (int o = 16; o; o >>= 1) v += __shfl_xor_sync(0xffffffffu, v, o);
        if (lane == 0) atomicAdd(&s_acc[52], v);
    }
    __syncthreads();
    for (int j = threadIdx.x; j < 56; j += 128) d_stats[gph * 56 + j] = s_acc[j];
}

// ---------------- K3: segment sum of x + fused tiny emb GEMM + mean ----------
__global__ void k_pool(const float* __restrict__ x,
                       const float* __restrict__ netW, const float* __restrict__ netb,
                       const float* __restrict__ devW, const float* __restrict__ devb,
                       const float* __restrict__ pinE) {
    int gph = blockIdx.x;
    int s0 = d_starts[gph], s1 = d_starts[gph + 1];

    __shared__ float st[56];
    for (int j = threadIdx.x; j < 56; j += 256) st[j] = d_stats[gph * 56 + j];
    __syncthreads();

    int c4 = threadIdx.x;
    const float4* x4 = (const float4*)x;
    float4 acc = make_float4(0.f, 0.f, 0.f, 0.f);

    #pragma unroll 4
    for (int r = s0; r < s1; r++) {
        float4 v = x4[(long)r * 256 + c4];
        acc.x += v.x; acc.y += v.y; acc.z += v.z; acc.w += v.w;
    }

    const float4* nW4 = (const float4*)netW;
    const float4* dW4 = (const float4*)devW;
    const float4* pE4 = (const float4*)pinE;
    float4 e = make_float4(0.f, 0.f, 0.f, 0.f);
    #pragma unroll
    for (int k = 0; k < NA; k++) {
        float4 wn = nW4[k * 256 + c4];
        float4 wd = dW4[k * 256 + c4];
        float4 wp = pE4[k * 256 + c4];
        float a0 = st[k], a1 = st[NA + k], cc = st[2 * NA + k];
        e.x += a0 * wn.x + a1 * wd.x + cc * wp.x;
        e.y += a0 * wn.y + a1 * wd.y + cc * wp.y;
        e.z += a0 * wn.z + a1 * wd.z + cc * wp.z;
        e.w += a0 * wn.w + a1 * wd.w + cc * wp.w;
    }
    float n0 = st[51], n1 = st[52];
    float4 nb = ((const float4*)netb)[c4];
    float4 db = ((const float4*)devb)[c4];
    e.x += n0 * nb.x + n1 * db.x;
    e.y += n0 * nb.y + n1 * db.y;
    e.z += n0 * nb.z + n1 * db.z;
    e.w += n0 * nb.w + n1 * db.w;

    float inv = 1.f / fmaxf((float)(s1 - s0), 1.f);
    float4 o;
    o.x = (acc.x + e.x) * inv;
    o.y = (acc.y + e.y) * inv;
    o.z = (acc.z + e.z) * inv;
    o.w = (acc.w + e.w) * inv;
    ((float4*)d_pooled)[(long)gph * 256 + c4] = o;
}

// ---------------- K4: split-K GEMM, 128x128 tile, 8x8/thread, plain fp32 -----
// smem bytes/FMA = 1.0 (balanced vs 128 B/cyc crossbar & 128 FMA/cyc pipe).
template<int SPLIT>
__global__ void __launch_bounds__(256, 2)
k_gemm8x8(const float* __restrict__ A, const float* __restrict__ W,
          float* __restrict__ part, int M, int N, int K) {
    const int kChunk = K / SPLIT;
    __shared__ float As[16][132];   // pad 4: float4-aligned rows, low-conflict stores
    __shared__ float Bs[16][132];

    int tid = threadIdx.x;
    int tx = tid & 15;        // col group: 8 cols
    int ty = tid >> 4;        // row group: 8 rows
    int n0 = blockIdx.x * 128, m0 = blockIdx.y * 128;
    int k0 = blockIdx.z * kChunk, kend = k0 + kChunk;

    float acc[8][8];
    #pragma unroll
    for (int i = 0; i < 8; i++)
        #pragma unroll
        for (int j = 0; j < 8; j++) acc[i][j] = 0.f;

    for (int kb = k0; kb < kend; kb += 16) {
        // A tile: 128 rows x 16 k. tid>>4 = row base, tid&15 = k.
        #pragma unroll
        for (int i = 0; i < 8; i++) {
            int idx = tid + i * 256;
            int m = idx >> 4, kk = idx & 15;
            As[kk][m] = A[(long)(m0 + m) * K + kb + kk];
        }
        // B tile: 16 k x 128 n. consecutive tid -> consecutive n (coalesced).
        #pragma unroll
        for (int i = 0; i < 8; i++) {
            int idx = tid + i * 256;
            int kk = idx >> 7, n = idx & 127;
            Bs[kk][n] = W[(long)(kb + kk) * N + n0 + n];
        }
        __syncthreads();

        #pragma unroll
        for (int kk = 0; kk < 16; kk++) {
            float4 a0 = *(const float4*)&As[kk][ty * 8];
            float4 a1 = *(const float4*)&As[kk][ty * 8 + 4];
            float4 b0 = *(const float4*)&Bs[kk][tx * 8];
            float4 b1 = *(const float4*)&Bs[kk][tx * 8 + 4];
            float av[8] = {a0.x, a0.y, a0.z, a0.w, a1.x, a1.y, a1.z, a1.w};
            float bv[8] = {b0.x, b0.y, b0.z, b0.w, b1.x, b1.y, b1.z, b1.w};
            #pragma unroll
            for (int i = 0; i < 8; i++)
                #pragma unroll
                for (int j = 0; j < 8; j++)
                    acc[i][j] += av[i] * bv[j];
        }
        __syncthreads();
    }

    float* dst = part + (long)blockIdx.z * M * N;
    int c0 = n0 + tx * 8;
    #pragma unroll
    for (int i = 0; i < 8; i++) {
        int m = m0 + ty * 8 + i;
        *(float4*)&dst[(long)m * N + c0]     = make_float4(acc[i][0], acc[i][1], acc[i][2], acc[i][3]);
        *(float4*)&dst[(long)m * N + c0 + 4] = make_float4(acc[i][4], acc[i][5], acc[i][6], acc[i][7]);
    }
}

// ---------------- K5: combine split-K + bias + relu + column stats -----------
template<int SPLIT>
__global__ void k_combine_stats(const float* __restrict__ part, const float* __restrict__ bias,
                                float* __restrict__ out, int MN, int N) {
    int tx = threadIdx.x & 15;
    int ty = threadIdx.x >> 4;
    int c4 = blockIdx.x * 16 + tx;
    int rbase = blockIdx.y * 128;
    int N4 = N >> 2;

    float4 bb = ((const float4*)bias)[c4];
    float4 sum = make_float4(0.f, 0.f, 0.f, 0.f);
    float4 sq  = make_float4(0.f, 0.f, 0.f, 0.f);

    for (int r = rbase + ty; r < rbase + 128; r += 16) {
        float4 v = make_float4(0.f, 0.f, 0.f, 0.f);
        long base = (long)r * N4 + c4;
        #pragma unroll
        for (int s = 0; s < SPLIT; s++) {
            float4 p = ((const float4*)part)[(long)s * (MN >> 2) + base];
            v.x += p.x; v.y += p.y; v.z += p.z; v.w += p.w;
        }
        v.x = fmaxf(v.x + bb.x, 0.f);
        v.y = fmaxf(v.y + bb.y, 0.f);
        v.z = fmaxf(v.z + bb.z, 0.f);
        v.w = fmaxf(v.w + bb.w, 0.f);
        ((float4*)out)[base] = v;
        sum.x += v.x; sum.y += v.y; sum.z += v.z; sum.w += v.w;
        sq.x += v.x * v.x; sq.y += v.y * v.y; sq.z += v.z * v.z; sq.w += v.w * v.w;
    }

    __shared__ float4 ssum[16][16], ssq[16][16];
    ssum[ty][tx] = sum; ssq[ty][tx] = sq;
    __syncthreads();
    if (ty == 0) {
        float4 S = ssum[0][tx], Q = ssq[0][tx];
        #pragma unroll
        for (int j = 1; j < 16; j++) {
            float4 s2 = ssum[j][tx], q2 = ssq[j][tx];
            S.x += s2.x; S.y += s2.y; S.z += s2.z; S.w += s2.w;
            Q.x += q2.x; Q.y += q2.y; Q.z += q2.z; Q.w += q2.w;
        }
        int col = c4 * 4;
        *(float4*)&d_bnsum[blockIdx.y * N + col] = S;
        *(float4*)&d_bnsq[blockIdx.y * N + col] = Q;
    }
}

// ---------------- K6: finalize BN -> scale/shift ------------------------------
__global__ void k_bnfinal(const float* __restrict__ g, const float* __restrict__ b, int N) {
    int c = blockIdx.x * blockDim.x + threadIdx.x;
    if (c >= N) return;
    float s = 0.f, q = 0.f;
    #pragma unroll
    for (int ch = 0; ch < 8; ch++) { s += d_bnsum[ch * N + c]; q += d_bnsq[ch * N + c]; }
    float m = s / (float)GG;
    float var = q / (float)GG - m * m;
    float rs = rsqrtf(var + EPS);
    float sc = rs * g[c];
    d_scale[c] = sc;
    d_shift[c] = b[c] - m * sc;
}

// ---------------- K6b: fold BN0 into fc1 weights ------------------------------
__global__ void k_foldW1(const float* __restrict__ W1) {
    int i = blockIdx.x * 256 + threadIdx.x;
    int k = i >> 8;
    d_w1p[i] = W1[i] * d_scale[k];
}
__global__ void k_foldb1a(const float* __restrict__ W1) {
    int b = blockIdx.x;
    int n = threadIdx.x & 255;
    float s = 0.f;
    int kbase = b * 64;
    #pragma unroll 8
    for (int k = 0; k < 64; k++)
        s += d_shift[kbase + k] * W1[(long)(kbase + k) * (DD / 4) + n];
    d_b1pp[b][n] = s;
}
__global__ void k_foldb1b(const float* __restrict__ b1) {
    int n = threadIdx.x;
    float s = b1[n];
    #pragma unroll
    for (int b = 0; b < 8; b++) s += d_b1pp[b][n];
    d_b1p[n] = s;
}

// ---------------- K7: fc2 dot(256) with fused BN1 + output assembly ----------
__global__ void k_head_out(const float* __restrict__ R1, const float* __restrict__ w,
                           const float* __restrict__ b, const float* __restrict__ y_reg,
                           float* __restrict__ out, int out_size) {
    int warp = (blockIdx.x * blockDim.x + threadIdx.x) >> 5;
    int lane = threadIdx.x & 31;
    if (warp >= GG) return;
    float s = 0.f;
    #pragma unroll
    for (int k = lane; k < DD / 4; k += 32) {
        float h = R1[(long)warp * (DD / 4) + k] * d_scale[k] + d_shift[k];
        s += h * w[k];
    }
    #pragma unroll
    for (int o = 16; o; o >>= 1) s += __shfl_xor_sync(0xffffffffu, s, o);
    if (lane == 0) {
        out[warp] = s + b[0];
        if (out_size >= 2 * GG) out[GG + warp] = y_reg[warp];
    }
}

// ---------------- launch ------------------------------------------------------
extern "C" void kernel_launch(void* const* d_in, const int* in_sizes, int n_in,
                              void* d_out, int out_size) {
    const float* x        = (const float*)d_in[0];
    const float* nattr    = (const float*)d_in[1];
    const int*   ntype    = (const int*)d_in[2];
    const int*   batch    = (const int*)d_in[3];
    const float* y_reg    = (const float*)d_in[4];
    const float* net_W    = (const float*)d_in[5];
    const float* net_b    = (const float*)d_in[6];
    const float* dev_W    = (const float*)d_in[7];
    const float* dev_b    = (const float*)d_in[8];
    const float* pin_emb  = (const float*)d_in[9];
    const float* fc0_W    = (const float*)d_in[10];
    const float* fc0_b    = (const float*)d_in[11];
    const float* fc1_W    = (const float*)d_in[12];
    const float* fc1_b    = (const float*)d_in[13];
    const float* fc2_W    = (const float*)d_in[14];
    const float* fc2_b    = (const float*)d_in[15];
    const float* bn0_g    = (const float*)d_in[16];
    const float* bn0_b    = (const float*)d_in[17];
    const float* bn1_g    = (const float*)d_in[18];
    const float* bn1_b    = (const float*)d_in[19];
    float* out = (float*)d_out;

    float *p_pooled, *p_part, *p_r0, *p_r1, *p_w1p, *p_b1p;
    cudaGetSymbolAddress((void**)&p_pooled, d_pooled);
    cudaGetSymbolAddress((void**)&p_part, d_part);
    cudaGetSymbolAddress((void**)&p_r0, d_r0);
    cudaGetSymbolAddress((void**)&p_r1, d_r1);
    cudaGetSymbolAddress((void**)&p_w1p, d_w1p);
    cudaGetSymbolAddress((void**)&p_b1p, d_b1p);

    const int N0 = DD / 2;   // 512
    const int N1 = DD / 4;   // 256
    const int MN0 = GG * N0;
    const int MN1 = GG * N1;

    k_find_starts<<<(GG + 1 + 255) / 256, 256>>>(batch);
    k_stats<<<GG, 128>>>(nattr, ntype);
    k_pool<<<GG, 256>>>(x, net_W, net_b, dev_W, dev_b, pin_emb);

    // fc0: 1024x512x1024, 128x128 tiles, split-K 8 -> 4x8x8 = 256 blocks (2 CTA/SM)
    k_gemm8x8<8><<<dim3(N0 / 128, GG / 128, 8), 256>>>(p_pooled, fc0_W, p_part, GG, N0, DD);
    k_combine_stats<8><<<dim3(N0 / 64, 8), 256>>>(p_part, fc0_b, p_r0, MN0, N0);
    k_bnfinal<<<(N0 + 255) / 256, 256>>>(bn0_g, bn0_b, N0);
    k_foldW1<<<(N0 * N1) / 256, 256>>>(fc1_W);
    k_foldb1a<<<8, 256>>>(fc1_W);
    k_foldb1b<<<1, N1>>>(fc1_b);

    // fc1: 1024x256x512 on folded weights, split-K 16 -> 2x8x16 = 256 blocks
    k_gemm8x8<16><<<dim3(N1 / 128, GG / 128, 16), 256>>>(p_r0, p_w1p, p_part, GG, N1, N0);
    k_combine_stats<16><<<dim3(N1 / 64, 8), 256>>>(p_part, p_b1p, p_r1, MN1, N1);
    k_bnfinal<<<(N1 + 255) / 256, 256>>>(bn1_g, bn1_b, N1);

    k_head_out<<<(GG * 32 + 255) / 256, 256>>>(p_r1, fc2_W, fc2_b, y_reg, out, out_size);
}